// round 9
// baseline (speedup 1.0000x reference)
#include <cuda_runtime.h>
#include <cuda_fp16.h>
#include <cstdint>
#include <cstddef>

// ============================================================================
// Fused LSTM cell, sm_103: fp16 mma.m16n8k16 + ldmatrix.
//  R9: warp tile 64x64 (CTA 256x128, 8 warps, 1 CTA/SM, NST=3 x 48KB smem).
//  MMA:LDSM ratio 16:6 -> 32:8. Gate-interleaved W16 + register-local epilogue
//  and bias-in-accumulator init carried over from R8.
// ============================================================================

#define BATCH 16384
#define HID   512
#define KD    1024
#define BK    64
#define NST   3
#define NITER (KD / BK)            // 16
#define STAGE_BYTES 49152          // A 256x64 fp16 (32KB) + B 128x64 (16KB)
#define B_OFF       32768
#define DYN_BYTES   147456         // 3 stages

__device__ __align__(256) __half g_A16[(size_t)BATCH * KD];     // 32 MB
__device__ __align__(256) __half g_W16[(size_t)2048  * KD];     // 4 MB

// ---------------------------------------------------------------------------
__device__ __forceinline__ uint32_t s2u(const void* p) {
    uint32_t a;
    asm("{ .reg .u64 t; cvta.to.shared.u64 t, %1; cvt.u32.u64 %0, t; }"
        : "=r"(a) : "l"(p));
    return a;
}
__device__ __forceinline__ void cp16(uint32_t dst, const void* src) {
    asm volatile("cp.async.cg.shared.global [%0], [%1], 16;"
                 :: "r"(dst), "l"(src));
}
__device__ __forceinline__ void ldm_x4(uint32_t* d, uint32_t a) {
    asm volatile("ldmatrix.sync.aligned.m8n8.x4.shared.b16 {%0,%1,%2,%3}, [%4];"
                 : "=r"(d[0]), "=r"(d[1]), "=r"(d[2]), "=r"(d[3]) : "r"(a));
}
__device__ __forceinline__ void mma16816(float* d, const uint32_t* a,
                                         const uint32_t* b) {
    asm volatile(
        "mma.sync.aligned.m16n8k16.row.col.f32.f16.f16.f32 "
        "{%0,%1,%2,%3}, {%4,%5,%6,%7}, {%8,%9}, {%0,%1,%2,%3};"
        : "+f"(d[0]), "+f"(d[1]), "+f"(d[2]), "+f"(d[3])
        : "r"(a[0]), "r"(a[1]), "r"(a[2]), "r"(a[3]), "r"(b[0]), "r"(b[1]));
}
__device__ __forceinline__ float sigmoid_f(float x) {
    return 1.0f / (1.0f + __expf(-x));
}
__device__ __forceinline__ float tanh_f(float x) {
    float e = __expf(2.0f * x);
    return 1.0f - 2.0f / (e + 1.0f);
}
// smem byte offset for (row, 16B-chunk), rows are 128B (8 chunks), xor swizzle
__device__ __forceinline__ uint32_t sw(int r, int c) {
    return (uint32_t)(r * 128 + ((c ^ (r & 7)) << 4));
}

// ---------------------------------------------------------------------------
// merged pre-pass: blocks [0,4096) convert A, blocks [4096,4608) convert W.
__global__ void __launch_bounds__(256) convAW(const float* __restrict__ ph,
                                              const float* __restrict__ xin,
                                              const float* __restrict__ Wi,
                                              const float* __restrict__ Wf,
                                              const float* __restrict__ Wo,
                                              const float* __restrict__ Wg) {
    if (blockIdx.x < 4096) {
        const size_t idx = (size_t)blockIdx.x * 256 + threadIdx.x;  // 1M thr
        #pragma unroll
        for (int j = 0; j < 4; ++j) {
            const size_t i = idx + (size_t)j * 1048576;             // 4M groups
            const int row = (int)(i >> 8);
            const int col = (int)(i & 255) * 4;
            const float* s = (col < 512) ? (ph + (size_t)row * 512 + col)
                                         : (xin + (size_t)row * 512 + (col - 512));
            const float4 v = *(const float4*)s;
            __half2 h0 = __floats2half2_rn(v.x, v.y);
            __half2 h1 = __floats2half2_rn(v.z, v.w);
            uint2 u;
            u.x = *reinterpret_cast<uint32_t*>(&h0);
            u.y = *reinterpret_cast<uint32_t*>(&h1);
            *(uint2*)(g_A16 + i * 4) = u;
        }
    } else {
        const size_t idx = (size_t)(blockIdx.x - 4096) * 256 + threadIdx.x;
        #pragma unroll
        for (int j = 0; j < 4; ++j) {
            const size_t i = idx + (size_t)j * 131072;              // 512K groups
            const int orow = (int)(i >> 8);
            const int col  = (int)(i & 255) * 4;
            const int ht = orow >> 7, r = orow & 127;
            // gate-interleaved: gate = bits[3:4], h = b6*16 + b5*8 + b[0:2]
            const int gate = (r >> 3) & 3;
            const int h    = ((r >> 6) << 4) + (((r >> 5) & 1) << 3) + (r & 7);
            const int hrow = ht * 32 + h;
            const float* W = (gate == 0) ? Wi : (gate == 1) ? Wf
                           : (gate == 2) ? Wo : Wg;
            const float4 v = *(const float4*)(W + (size_t)hrow * KD + col);
            __half2 h0 = __floats2half2_rn(v.x, v.y);
            __half2 h1 = __floats2half2_rn(v.z, v.w);
            uint2 u;
            u.x = *reinterpret_cast<uint32_t*>(&h0);
            u.y = *reinterpret_cast<uint32_t*>(&h1);
            *(uint2*)(g_W16 + i * 4) = u;
        }
    }
}

// ---------------------------------------------------------------------------
__global__ void __launch_bounds__(256, 1)
lstm_fp16_gemm(const float* __restrict__ prev_c,
               const float* __restrict__ bi, const float* __restrict__ bf,
               const float* __restrict__ bo, const float* __restrict__ bg,
               float* __restrict__ h_out, float* __restrict__ c_out)
{
    extern __shared__ char smc[];
    const uint32_t sb = s2u(smc);

    const int tid = threadIdx.x;
    const int wid = tid >> 5;
    const int lid = tid & 31;
    const int hb  = blockIdx.x;            // 16 h-tiles (fastest: W hot in L2)
    const int mb  = blockIdx.y;            // 64 m-tiles (256 rows each)
    const int wm  = wid >> 1;              // 0..3 : 64 m-rows per warp
    const int wn  = wid & 1;               // 0..1 : 64 n-cols per warp

    // ---- cp.async mapping: 8 threads cover one 128B row ---------------------
    const int cr = tid >> 3;               // 0..31
    const int cc = tid & 7;                // chunk 0..7
    const __half* gA = g_A16 + (size_t)(mb * 256) * KD + cc * 8;
    const __half* gB = g_W16 + (size_t)(hb * 128) * KD + cc * 8;

    auto issue = [&](int kt) {
        const uint32_t so = sb + (uint32_t)(kt % NST) * STAGE_BYTES;
        const int kcol = kt * BK;
        #pragma unroll
        for (int i = 0; i < 8; ++i) {      // A: 256 rows
            const int r = cr + 32 * i;
            cp16(so + sw(r, cc), gA + (size_t)r * KD + kcol);
        }
        #pragma unroll
        for (int i = 0; i < 4; ++i) {      // B: 128 rows
            const int r = cr + 32 * i;
            cp16(so + B_OFF + sw(r, cc), gB + (size_t)r * KD + kcol);
        }
        asm volatile("cp.async.commit_group;" ::: "memory");
    };

    issue(0); issue(1);

    // ---- accumulators pre-loaded with biases --------------------------------
    // fragment ni: gate = ni&3 (i,f,o,g), h_octet = ni>>2
    float acc[4][8][4];
    {
        const int hq = hb * 32 + wn * 16 + (lid & 3) * 2;
        #pragma unroll
        for (int ni = 0; ni < 8; ++ni) {
            const int gate = ni & 3;
            const int h = hq + ((ni >> 2) << 3);
            const float* bp = (gate == 0) ? bi : (gate == 1) ? bf
                            : (gate == 2) ? bo : bg;
            const float b0 = __ldg(&bp[h]);
            const float b1 = __ldg(&bp[h + 1]);
            #pragma unroll
            for (int mi = 0; mi < 4; ++mi) {
                acc[mi][ni][0] = b0; acc[mi][ni][1] = b1;
                acc[mi][ni][2] = b0; acc[mi][ni][3] = b1;
            }
        }
    }

    // ldmatrix lane coordinates
    const int a_r = (lid & 15);
    const int a_c = (lid >> 4);
    const int b_r = ((lid >> 4) << 3) + (lid & 7);
    const int b_c = ((lid >> 3) & 1);

    #pragma unroll 1
    for (int it = 0; it < NITER; ++it) {
        if (it + 1 < NITER) asm volatile("cp.async.wait_group 1;" ::: "memory");
        else                asm volatile("cp.async.wait_group 0;" ::: "memory");
        __syncthreads();

        if (it + 2 < NITER) issue(it + 2);

        const uint32_t smA = sb + (uint32_t)(it % NST) * STAGE_BYTES;
        const uint32_t smB = smA + B_OFF;

        uint32_t a[2][4][4], b[2][8][2];   // double-buffered fragments
        {
            #pragma unroll
            for (int mi = 0; mi < 4; ++mi)
                ldm_x4(a[0][mi], smA + sw(wm * 64 + mi * 16 + a_r, a_c));
            #pragma unroll
            for (int n2 = 0; n2 < 4; ++n2) {
                uint32_t t4[4];
                ldm_x4(t4, smB + sw(wn * 64 + n2 * 16 + b_r, b_c));
                b[0][n2 * 2][0] = t4[0]; b[0][n2 * 2][1] = t4[1];
                b[0][n2 * 2 + 1][0] = t4[2]; b[0][n2 * 2 + 1][1] = t4[3];
            }
        }
        #pragma unroll
        for (int ks = 0; ks < 4; ++ks) {
            const int cur = ks & 1, nxt = cur ^ 1;
            if (ks < 3) {                  // preload ks+1 while mma'ing ks
                const int kc = (ks + 1) * 2;
                #pragma unroll
                for (int mi = 0; mi < 4; ++mi)
                    ldm_x4(a[nxt][mi], smA + sw(wm * 64 + mi * 16 + a_r, kc + a_c));
                #pragma unroll
                for (int n2 = 0; n2 < 4; ++n2) {
                    uint32_t t4[4];
                    ldm_x4(t4, smB + sw(wn * 64 + n2 * 16 + b_r, kc + b_c));
                    b[nxt][n2 * 2][0] = t4[0]; b[nxt][n2 * 2][1] = t4[1];
                    b[nxt][n2 * 2 + 1][0] = t4[2]; b[nxt][n2 * 2 + 1][1] = t4[3];
                }
            }
            #pragma unroll
            for (int mi = 0; mi < 4; ++mi)
                #pragma unroll
                for (int ni = 0; ni < 8; ++ni)
                    mma16816(acc[mi][ni], a[cur][mi], b[cur][ni]);
        }
    }

    // ---- register-local epilogue --------------------------------------------
    #pragma unroll
    for (int mi = 0; mi < 4; ++mi) {
        const int r_base = mb * 256 + wm * 64 + mi * 16 + (lid >> 2);
        #pragma unroll
        for (int ho = 0; ho < 2; ++ho) {
            const int hg = hb * 32 + wn * 16 + ho * 8 + (lid & 3) * 2;
            #pragma unroll
            for (int pr = 0; pr < 2; ++pr) {       // row +0 / +8
                const int r = r_base + pr * 8;
                const size_t off = (size_t)r * HID + hg;
                const float2 pc = *(const float2*)(prev_c + off);
                const int q0 = pr * 2, q1 = pr * 2 + 1;
                const float i0 = sigmoid_f(acc[mi][ho * 4 + 0][q0]);
                const float f0 = sigmoid_f(acc[mi][ho * 4 + 1][q0]);
                const float o0 = sigmoid_f(acc[mi][ho * 4 + 2][q0]);
                const float g0 = tanh_f   (acc[mi][ho * 4 + 3][q0]);
                const float i1 = sigmoid_f(acc[mi][ho * 4 + 0][q1]);
                const float f1 = sigmoid_f(acc[mi][ho * 4 + 1][q1]);
                const float o1 = sigmoid_f(acc[mi][ho * 4 + 2][q1]);
                const float g1 = tanh_f   (acc[mi][ho * 4 + 3][q1]);
                const float c0 = f0 * pc.x + i0 * g0;
                const float c1 = f1 * pc.y + i1 * g1;
                *(float2*)(h_out + off) = make_float2(tanh_f(c0) * o0,
                                                      tanh_f(c1) * o1);
                *(float2*)(c_out + off) = make_float2(c0, c1);
            }
        }
    }
}

// ---------------------------------------------------------------------------
extern "C" void kernel_launch(void* const* d_in, const int* in_sizes, int n_in,
                              void* d_out, int out_size) {
    const float* input_ = (const float*)d_in[0];
    const float* prev_h = (const float*)d_in[1];
    const float* prev_c = (const float*)d_in[2];
    const float* W_i = (const float*)d_in[3];  const float* b_i = (const float*)d_in[4];
    const float* W_f = (const float*)d_in[5];  const float* b_f = (const float*)d_in[6];
    const float* W_g = (const float*)d_in[7];  const float* b_g = (const float*)d_in[8];
    const float* W_o = (const float*)d_in[9];  const float* b_o = (const float*)d_in[10];

    float* h_out = (float*)d_out;
    float* c_out = h_out + (size_t)BATCH * HID;

    convAW<<<4608, 256>>>(prev_h, input_, W_i, W_f, W_o, W_g);

    cudaFuncSetAttribute(lstm_fp16_gemm,
                         cudaFuncAttributeMaxDynamicSharedMemorySize, DYN_BYTES);
    dim3 grid(16, 64);
    lstm_fp16_gemm<<<grid, 256, DYN_BYTES>>>(prev_c, b_i, b_f, b_o, b_g,
                                             h_out, c_out);
}

// round 10
// speedup vs baseline: 1.3796x; 1.3796x over previous
#include <cuda_runtime.h>
#include <cuda_fp16.h>
#include <cstdint>
#include <cstddef>

// ============================================================================
// Fused LSTM cell, sm_103: fp16 mma.m16n8k16 + ldmatrix.
//  R10: R8 shape (CTA 128x128, warp 32x64, BK=64, NST=3, 2 CTA/SM) but the
//  mainloop barrier (wait_group + __syncthreads per iter) is replaced with an
//  mbarrier full/empty pipeline: full[s] fires via cp.async.mbarrier.arrive
//  .noinc (256 arrivals), empty[s] via per-thread arrive after last consuming
//  MMA. No __syncthreads in the mainloop; warps run decoupled.
// ============================================================================

#define BATCH 16384
#define HID   512
#define KD    1024
#define BK    64
#define NST   3
#define NITER (KD / BK)            // 16
#define STAGE_BYTES 32768          // A 128x64 fp16 (16KB) + B (16KB)
#define PIPE_OFF    98304          // barriers after 3 stages
#define DYN_BYTES   (98304 + 64)

__device__ __align__(256) __half g_A16[(size_t)BATCH * KD];     // 32 MB
__device__ __align__(256) __half g_W16[(size_t)2048  * KD];     // 4 MB

// ---------------------------------------------------------------------------
__device__ __forceinline__ uint32_t s2u(const void* p) {
    uint32_t a;
    asm("{ .reg .u64 t; cvta.to.shared.u64 t, %1; cvt.u32.u64 %0, t; }"
        : "=r"(a) : "l"(p));
    return a;
}
__device__ __forceinline__ void cp16(uint32_t dst, const void* src) {
    asm volatile("cp.async.cg.shared.global [%0], [%1], 16;"
                 :: "r"(dst), "l"(src));
}
__device__ __forceinline__ void ldm_x4(uint32_t* d, uint32_t a) {
    asm volatile("ldmatrix.sync.aligned.m8n8.x4.shared.b16 {%0,%1,%2,%3}, [%4];"
                 : "=r"(d[0]), "=r"(d[1]), "=r"(d[2]), "=r"(d[3]) : "r"(a));
}
__device__ __forceinline__ void mma16816(float* d, const uint32_t* a,
                                         const uint32_t* b) {
    asm volatile(
        "mma.sync.aligned.m16n8k16.row.col.f32.f16.f16.f32 "
        "{%0,%1,%2,%3}, {%4,%5,%6,%7}, {%8,%9}, {%0,%1,%2,%3};"
        : "+f"(d[0]), "+f"(d[1]), "+f"(d[2]), "+f"(d[3])
        : "r"(a[0]), "r"(a[1]), "r"(a[2]), "r"(a[3]), "r"(b[0]), "r"(b[1]));
}
__device__ __forceinline__ void bar_init(uint32_t bar, uint32_t cnt) {
    asm volatile("mbarrier.init.shared.b64 [%0], %1;" :: "r"(bar), "r"(cnt)
                 : "memory");
}
__device__ __forceinline__ void bar_wait(uint32_t bar, uint32_t parity) {
    asm volatile(
        "{\n\t.reg .pred P;\n\t"
        "WL%=:\n\t"
        "mbarrier.try_wait.parity.shared.b64 P, [%0], %1;\n\t"
        "@P bra WD%=;\n\t"
        "bra WL%=;\n\t"
        "WD%=:\n\t}"
        :: "r"(bar), "r"(parity) : "memory");
}
__device__ __forceinline__ void bar_arrive(uint32_t bar) {
    asm volatile("mbarrier.arrive.shared.b64 _, [%0];" :: "r"(bar) : "memory");
}
__device__ __forceinline__ void cp_arrive_noinc(uint32_t bar) {
    asm volatile("cp.async.mbarrier.arrive.noinc.shared.b64 [%0];"
                 :: "r"(bar) : "memory");
}
__device__ __forceinline__ float sigmoid_f(float x) {
    return 1.0f / (1.0f + __expf(-x));
}
__device__ __forceinline__ float tanh_f(float x) {
    float e = __expf(2.0f * x);
    return 1.0f - 2.0f / (e + 1.0f);
}
// smem byte offset for (row, 16B-chunk), rows are 128B (8 chunks), xor swizzle
__device__ __forceinline__ uint32_t sw(int r, int c) {
    return (uint32_t)(r * 128 + ((c ^ (r & 7)) << 4));
}

// ---------------------------------------------------------------------------
// merged pre-pass: blocks [0,4096) convert A, blocks [4096,4608) convert W.
__global__ void __launch_bounds__(256) convAW(const float* __restrict__ ph,
                                              const float* __restrict__ xin,
                                              const float* __restrict__ Wi,
                                              const float* __restrict__ Wf,
                                              const float* __restrict__ Wo,
                                              const float* __restrict__ Wg) {
    if (blockIdx.x < 4096) {
        const size_t idx = (size_t)blockIdx.x * 256 + threadIdx.x;  // 1M thr
        #pragma unroll
        for (int j = 0; j < 4; ++j) {
            const size_t i = idx + (size_t)j * 1048576;             // 4M groups
            const int row = (int)(i >> 8);
            const int col = (int)(i & 255) * 4;
            const float* s = (col < 512) ? (ph + (size_t)row * 512 + col)
                                         : (xin + (size_t)row * 512 + (col - 512));
            const float4 v = *(const float4*)s;
            __half2 h0 = __floats2half2_rn(v.x, v.y);
            __half2 h1 = __floats2half2_rn(v.z, v.w);
            uint2 u;
            u.x = *reinterpret_cast<uint32_t*>(&h0);
            u.y = *reinterpret_cast<uint32_t*>(&h1);
            *(uint2*)(g_A16 + i * 4) = u;
        }
    } else {
        const size_t idx = (size_t)(blockIdx.x - 4096) * 256 + threadIdx.x;
        #pragma unroll
        for (int j = 0; j < 4; ++j) {
            const size_t i = idx + (size_t)j * 131072;              // 512K groups
            const int orow = (int)(i >> 8);
            const int col  = (int)(i & 255) * 4;
            const int ht = orow >> 7, r = orow & 127;
            // gate-interleaved: gate = bits[3:4], h = b6*16 + b5*8 + b[0:2]
            const int gate = (r >> 3) & 3;
            const int h    = ((r >> 6) << 4) + (((r >> 5) & 1) << 3) + (r & 7);
            const int hrow = ht * 32 + h;
            const float* W = (gate == 0) ? Wi : (gate == 1) ? Wf
                           : (gate == 2) ? Wo : Wg;
            const float4 v = *(const float4*)(W + (size_t)hrow * KD + col);
            __half2 h0 = __floats2half2_rn(v.x, v.y);
            __half2 h1 = __floats2half2_rn(v.z, v.w);
            uint2 u;
            u.x = *reinterpret_cast<uint32_t*>(&h0);
            u.y = *reinterpret_cast<uint32_t*>(&h1);
            *(uint2*)(g_W16 + i * 4) = u;
        }
    }
}

// ---------------------------------------------------------------------------
__global__ void __launch_bounds__(256, 2)
lstm_fp16_gemm(const float* __restrict__ prev_c,
               const float* __restrict__ bi, const float* __restrict__ bf,
               const float* __restrict__ bo, const float* __restrict__ bg,
               float* __restrict__ h_out, float* __restrict__ c_out)
{
    extern __shared__ char smc[];
    const uint32_t sb = s2u(smc);
    const uint32_t FULLB  = sb + PIPE_OFF;        // full[s]  at +0,8,16
    const uint32_t EMPTYB = sb + PIPE_OFF + 24;   // empty[s] at +0,8,16

    const int tid = threadIdx.x;
    const int wid = tid >> 5;
    const int lid = tid & 31;
    const int hb  = blockIdx.x;            // 16 h-tiles (fastest: W hot in L2)
    const int mb  = blockIdx.y;            // 128 m-tiles
    const int wm  = wid >> 1;              // 0..3
    const int wn  = wid & 1;               // 0..1

    if (tid == 0) {
        #pragma unroll
        for (int s = 0; s < NST; ++s) {
            bar_init(FULLB  + 8 * s, 256);
            bar_init(EMPTYB + 8 * s, 256);
        }
    }
    __syncthreads();

    // ---- cp.async mapping: 8 threads cover one 128B row ---------------------
    const int cr = tid >> 3;               // 0..31
    const int cc = tid & 7;                // chunk 0..7
    const __half* gA = g_A16 + (size_t)(mb * 128) * KD + cc * 8;
    const __half* gB = g_W16 + (size_t)(hb * 128) * KD + cc * 8;

    auto produce = [&](int kt) {
        const int s2 = kt % NST;
        const uint32_t so = sb + (uint32_t)s2 * STAGE_BYTES;
        const int kcol = kt * BK;
        #pragma unroll
        for (int i = 0; i < 4; ++i) {
            const int r = cr + 32 * i;
            cp16(so + sw(r, cc),         gA + (size_t)r * KD + kcol);
            cp16(so + 16384 + sw(r, cc), gB + (size_t)r * KD + kcol);
        }
        cp_arrive_noinc(FULLB + 8 * s2);
    };

    produce(0);
    produce(1);

    // ---- accumulators pre-loaded with biases --------------------------------
    float acc[2][8][4];
    {
        const int hq = hb * 32 + wn * 16 + (lid & 3) * 2;
        #pragma unroll
        for (int ni = 0; ni < 8; ++ni) {
            const int gate = ni & 3;
            const int h = hq + ((ni >> 2) << 3);
            const float* bp = (gate == 0) ? bi : (gate == 1) ? bf
                            : (gate == 2) ? bo : bg;
            const float b0 = __ldg(&bp[h]);
            const float b1 = __ldg(&bp[h + 1]);
            #pragma unroll
            for (int mi = 0; mi < 2; ++mi) {
                acc[mi][ni][0] = b0; acc[mi][ni][1] = b1;
                acc[mi][ni][2] = b0; acc[mi][ni][3] = b1;
            }
        }
    }

    // ldmatrix lane coordinates
    const int a_r = (lid & 15);
    const int a_c = (lid >> 4);
    const int b_r = ((lid >> 4) << 3) + (lid & 7);
    const int b_c = ((lid >> 3) & 1);

    #pragma unroll 1
    for (int it = 0; it < NITER; ++it) {
        const int s = it % NST;
        const int u = it / NST;

        // producer for stage it+2 (wait for stage free, then fill)
        if (it + 2 < NITER) {
            const int i2 = it + 2;
            if (i2 >= NST) {
                const int u2 = i2 / NST;
                bar_wait(EMPTYB + 8 * (i2 % NST), (u2 - 1) & 1);
            }
            produce(i2);
        }

        // consumer: wait until ALL threads' copies for stage s landed
        bar_wait(FULLB + 8 * s, u & 1);

        const uint32_t smA = sb + (uint32_t)s * STAGE_BYTES;
        const uint32_t smB = smA + 16384;

        uint32_t a[2][2][4], b[2][8][2];   // double-buffered fragments
        {
            #pragma unroll
            for (int mi = 0; mi < 2; ++mi)
                ldm_x4(a[0][mi], smA + sw(wm * 32 + mi * 16 + a_r, a_c));
            #pragma unroll
            for (int n2 = 0; n2 < 4; ++n2) {
                uint32_t t4[4];
                ldm_x4(t4, smB + sw(wn * 64 + n2 * 16 + b_r, b_c));
                b[0][n2 * 2][0] = t4[0]; b[0][n2 * 2][1] = t4[1];
                b[0][n2 * 2 + 1][0] = t4[2]; b[0][n2 * 2 + 1][1] = t4[3];
            }
        }
        #pragma unroll
        for (int ks = 0; ks < 4; ++ks) {
            const int cur = ks & 1, nxt = cur ^ 1;
            if (ks < 3) {                  // preload ks+1 while mma'ing ks
                const int kc = (ks + 1) * 2;
                #pragma unroll
                for (int mi = 0; mi < 2; ++mi)
                    ldm_x4(a[nxt][mi], smA + sw(wm * 32 + mi * 16 + a_r, kc + a_c));
                #pragma unroll
                for (int n2 = 0; n2 < 4; ++n2) {
                    uint32_t t4[4];
                    ldm_x4(t4, smB + sw(wn * 64 + n2 * 16 + b_r, kc + b_c));
                    b[nxt][n2 * 2][0] = t4[0]; b[nxt][n2 * 2][1] = t4[1];
                    b[nxt][n2 * 2 + 1][0] = t4[2]; b[nxt][n2 * 2 + 1][1] = t4[3];
                }
            }
            #pragma unroll
            for (int mi = 0; mi < 2; ++mi)
                #pragma unroll
                for (int ni = 0; ni < 8; ++ni)
                    mma16816(acc[mi][ni], a[cur][mi], b[cur][ni]);
        }
        // all smem reads of stage s are complete (MMAs consumed the LDSM regs)
        bar_arrive(EMPTYB + 8 * s);
    }

    // ---- register-local epilogue --------------------------------------------
    #pragma unroll
    for (int mi = 0; mi < 2; ++mi) {
        const int r_base = mb * 128 + wm * 32 + mi * 16 + (lid >> 2);
        #pragma unroll
        for (int ho = 0; ho < 2; ++ho) {
            const int hg = hb * 32 + wn * 16 + ho * 8 + (lid & 3) * 2;
            #pragma unroll
            for (int pr = 0; pr < 2; ++pr) {       // row +0 / +8
                const int r = r_base + pr * 8;
                const size_t off = (size_t)r * HID + hg;
                const float2 pc = *(const float2*)(prev_c + off);
                const int q0 = pr * 2, q1 = pr * 2 + 1;
                const float i0 = sigmoid_f(acc[mi][ho * 4 + 0][q0]);
                const float f0 = sigmoid_f(acc[mi][ho * 4 + 1][q0]);
                const float o0 = sigmoid_f(acc[mi][ho * 4 + 2][q0]);
                const float g0 = tanh_f   (acc[mi][ho * 4 + 3][q0]);
                const float i1 = sigmoid_f(acc[mi][ho * 4 + 0][q1]);
                const float f1 = sigmoid_f(acc[mi][ho * 4 + 1][q1]);
                const float o1 = sigmoid_f(acc[mi][ho * 4 + 2][q1]);
                const float g1 = tanh_f   (acc[mi][ho * 4 + 3][q1]);
                const float c0 = f0 * pc.x + i0 * g0;
                const float c1 = f1 * pc.y + i1 * g1;
                *(float2*)(h_out + off) = make_float2(tanh_f(c0) * o0,
                                                      tanh_f(c1) * o1);
                *(float2*)(c_out + off) = make_float2(c0, c1);
            }
        }
    }
}

// ---------------------------------------------------------------------------
extern "C" void kernel_launch(void* const* d_in, const int* in_sizes, int n_in,
                              void* d_out, int out_size) {
    const float* input_ = (const float*)d_in[0];
    const float* prev_h = (const float*)d_in[1];
    const float* prev_c = (const float*)d_in[2];
    const float* W_i = (const float*)d_in[3];  const float* b_i = (const float*)d_in[4];
    const float* W_f = (const float*)d_in[5];  const float* b_f = (const float*)d_in[6];
    const float* W_g = (const float*)d_in[7];  const float* b_g = (const float*)d_in[8];
    const float* W_o = (const float*)d_in[9];  const float* b_o = (const float*)d_in[10];

    float* h_out = (float*)d_out;
    float* c_out = h_out + (size_t)BATCH * HID;

    convAW<<<4608, 256>>>(prev_h, input_, W_i, W_f, W_o, W_g);

    cudaFuncSetAttribute(lstm_fp16_gemm,
                         cudaFuncAttributeMaxDynamicSharedMemorySize, DYN_BYTES);
    dim3 grid(16, 128);
    lstm_fp16_gemm<<<grid, 256, DYN_BYTES>>>(prev_c, b_i, b_f, b_o, b_g,
                                             h_out, c_out);
}